// round 13
// baseline (speedup 1.0000x reference)
#include <cuda_runtime.h>
#include <cuda_bf16.h>
#include <math.h>

#define NB 65536
#define LH 64
#define GOALC 0.5f
#define MINPC (-1.2f)
#define UTHRESH 0.5f

typedef unsigned long long u64;

// ---- packed f32x2 primitives (single-slot FFMA2/FADD2/FMUL2 on sm_103a) ----
__device__ __forceinline__ u64 pk2(float lo, float hi) {
    u64 r; asm("mov.b64 %0, {%1, %2};" : "=l"(r) : "f"(lo), "f"(hi)); return r;
}
__device__ __forceinline__ void upk2(u64 v, float& lo, float& hi) {
    asm("mov.b64 {%0, %1}, %2;" : "=f"(lo), "=f"(hi) : "l"(v));
}
__device__ __forceinline__ u64 mul2(u64 a, u64 b) {
    u64 r; asm("mul.rn.f32x2 %0, %1, %2;" : "=l"(r) : "l"(a), "l"(b)); return r;
}
__device__ __forceinline__ u64 fma2(u64 a, u64 b, u64 c) {
    u64 r; asm("fma.rn.f32x2 %0, %1, %2, %3;" : "=l"(r) : "l"(a), "l"(b), "l"(c)); return r;
}
__device__ __forceinline__ u64 add2(u64 a, u64 b) {
    u64 r; asm("add.rn.f32x2 %0, %1, %2;" : "=l"(r) : "l"(a), "l"(b)); return r;
}

// XLA / Eigen rational tanh approximation for f32 (matches reference lowering).
__device__ __forceinline__ float xla_tanh(float xin) {
    const float x = fminf(fmaxf(xin, -7.99881172180175781f), 7.99881172180175781f);
    const float x2 = __fmul_rn(x, x);
    float p = __fmaf_rn(x2, -2.76076847742355e-16f, 2.00018790482477e-13f);
    p = __fmaf_rn(x2, p, -8.60467152213735e-11f);
    p = __fmaf_rn(x2, p, 5.12229709037114e-08f);
    p = __fmaf_rn(x2, p, 1.48572235717979e-05f);
    p = __fmaf_rn(x2, p, 6.37261928875436e-04f);
    p = __fmaf_rn(x2, p, 4.89352455891786e-03f);
    p = __fmul_rn(x, p);
    float q = __fmaf_rn(x2, 1.19825839466702e-06f, 1.18534705686654e-04f);
    q = __fmaf_rn(x2, q, 2.26843463243900e-03f);
    q = __fmaf_rn(x2, q, 4.89352518554385e-03f);
    const float r = __fdiv_rn(p, q);
    return (fabsf(xin) < 0.0004f) ? xin : r;
}

// fp32 cos (|x| <= ~3.8), Cody-Waite with residual carry, ~1-1.5 ulp.
__device__ __forceinline__ float cos_cw(float x) {
    const float kf = rintf(__fmul_rn(x, 0.63661977236758134f));
    const int k = (int)kf;
    const float DP1 = 1.5703125f;
    const float DP2 = 4.837512969970703125e-4f;
    const float DP3 = 7.549789948768648e-8f;
    const float t  = __fmaf_rn(-kf, DP1, x);
    const float rh = __fmaf_rn(-kf, DP2, t);
    float rl = __fsub_rn(__fsub_rn(t, rh), __fmul_rn(kf, DP2));
    rl = __fmaf_rn(-kf, DP3, rl);
    const float z = __fmul_rn(rh, rh);

    float pc = __fmaf_rn(z, 2.443315711809948e-5f, -1.388731625493765e-3f);
    pc = __fmaf_rn(z, pc, 4.166664568298827e-2f);
    float c = __fmaf_rn(z, -0.5f, 1.0f);
    c = __fmaf_rn(__fmul_rn(z, z), pc, c);
    c = __fmaf_rn(-rl, rh, c);

    float ps = __fmaf_rn(z, -1.9515295891e-4f, 8.3321608736e-3f);
    ps = __fmaf_rn(z, ps, -1.6666654611e-1f);
    float s = __fmaf_rn(__fmul_rn(rh, z), ps, rl);
    s = __fadd_rn(rh, s);

    const int q = k & 3;
    float r = (q & 1) ? s : c;
    if (q == 1 || q == 2) r = -r;
    return r;
}

// Largest float T in [0.4, 1.0] with xla_tanh(T) <= UTHRESH (bit bisection).
__device__ __forceinline__ float tanh_threshold() {
    unsigned a = __float_as_uint(0.4f);
    unsigned b = __float_as_uint(1.0f);
    while (b - a > 1u) {
        const unsigned m = a + (b - a) / 2u;
        if (xla_tanh(__uint_as_float(m)) <= UTHRESH) a = m; else b = m;
    }
    return __uint_as_float(a);
}

// Shared weight layout — packed by UNIT PAIRS (no duplication), as in R10-R12:
//   wxy[m] = { {W1[0][2m], W1[0][2m+1]}, {W1[1][2m], W1[1][2m+1]} }   m=0..31
//   wzh[q] = { {W2[4q]/2, W2[4q+1]/2}, {W2[4q+2]/2, W2[4q+3]/2} }     q=0..15
//   wbb[m] = { b1[2m], b1[2m+1] }
// Unit j accumulates into scalar lane (j mod 8) in increasing-j order,
// then the R6 scalar rn merge tree -> bit-identical to R6/R10/R11/R12.
template<bool B1_ZERO>
__device__ __forceinline__ void run_agent(
    const ulonglong2* __restrict__ wxy,
    const ulonglong2* __restrict__ wzh,
    const u64* __restrict__ wbb,
    float bias2, float T, int n,
    float& p, float& v, float& u, float& a)
{
    const u64 ABSM = 0x7FFFFFFF7FFFFFFFULL;
    float lastPre = 0.0f;
    bool took = false;

    for (int t = 0; t < n; ++t) {
        if (p > GOALC) break;   // inactive is absorbing

        const bool rs = (p <= MINPC);
        const float pr = rs ? MINPC : p;
        const float vr = rs ? 0.0f : v;

        const u64 p2 = pk2(pr, pr);
        const u64 v2 = pk2(vr, vr);

        // 4 packed accumulators = 8 scalar lanes (R6 mapping).
        // unroll 4 (of 16): 12 batched LDS.128 per chunk, fits 128-reg budget.
        u64 S0 = 0, S1 = 0, S2 = 0, S3 = 0;
        #pragma unroll 4
        for (int q = 0; q < LH / 4; ++q) {         // 4 units per iteration
            const ulonglong2 xy0 = wxy[2 * q];      // units 4q, 4q+1
            const ulonglong2 xy1 = wxy[2 * q + 1];  // units 4q+2, 4q+3
            const ulonglong2 zz  = wzh[q];

            u64 d0 = fma2(v2, xy0.y, mul2(p2, xy0.x));
            u64 d1 = fma2(v2, xy1.y, mul2(p2, xy1.x));
            if (!B1_ZERO) {
                d0 = add2(d0, wbb[2 * q]);
                d1 = add2(d1, wbb[2 * q + 1]);
            }
            // relu(d)*wz + acc == fma(d+|d|, wz/2, acc), single rounding (exact)
            const u64 r0 = add2(d0, d0 & ABSM);
            const u64 r1 = add2(d1, d1 & ABSM);

            if ((q & 1) == 0) {   // units 4q..4q+3 -> lanes 0..3
                S0 = fma2(r0, zz.x, S0);
                S1 = fma2(r1, zz.y, S1);
            } else {              // lanes 4..7
                S2 = fma2(r0, zz.x, S2);
                S3 = fma2(r1, zz.y, S3);
            }
        }

        // unpack to the 8 scalar lanes, then R6's exact rn merge tree
        float l0, l1, l2, l3, l4, l5, l6, l7;
        upk2(S0, l0, l1); upk2(S1, l2, l3); upk2(S2, l4, l5); upk2(S3, l6, l7);
        const float dot =
            __fadd_rn(__fadd_rn(__fadd_rn(l0, l1), __fadd_rn(l2, l3)),
                      __fadd_rn(__fadd_rn(l4, l5), __fadd_rn(l6, l7)));
        const float pre = __fadd_rn(dot, bias2);

        // un via hoisted tanh threshold (validated bit-exact R9-R12)
        const float un = (pre <= T) ? -1.0f : 1.0f;

        const float c  = cos_cw(__fmul_rn(3.0f, pr));
        const float vn = __fsub_rn(__fadd_rn(vr, __fmul_rn(un, 0.0015f)),
                                   __fmul_rn(0.0025f, c));
        const float pn = __fadd_rn(pr, vn);

        p = pn; v = vn; u = un; lastPre = pre; took = true;
    }

    if (took) a = xla_tanh(lastPre);
}

__global__ __launch_bounds__(64, 8)   // 128-reg budget -> 16 warps/SM resident
void mc_kernel(const float4* __restrict__ x,
               const float* __restrict__ W1,
               const float* __restrict__ b1,
               const float* __restrict__ W2,
               const float* __restrict__ b2,
               const int* __restrict__ n_steps,
               float4* __restrict__ out)
{
    __shared__ ulonglong2 wxy[LH / 2];
    __shared__ ulonglong2 wzh[LH / 4];
    __shared__ u64 wbb[LH / 2];

    const int tid = threadIdx.x;   // 0..63
    int zok = 1;
    if (tid < LH / 2) {
        const int j0 = 2 * tid, j1 = 2 * tid + 1;
        wxy[tid] = make_ulonglong2(pk2(W1[j0], W1[j1]),
                                   pk2(W1[LH + j0], W1[LH + j1]));
        const float bv0 = b1[j0], bv1 = b1[j1];
        wbb[tid] = pk2(bv0, bv1);
        zok = (__float_as_uint(bv0) == 0u) && (__float_as_uint(bv1) == 0u);
    }
    if (tid < LH / 4) {
        const int j = 4 * tid;
        wzh[tid] = make_ulonglong2(
            pk2(__fmul_rn(0.5f, W2[j]),     __fmul_rn(0.5f, W2[j + 1])),
            pk2(__fmul_rn(0.5f, W2[j + 2]), __fmul_rn(0.5f, W2[j + 3])));
    }
    const int b1_zero = __syncthreads_and(zok);

    const float bias2 = b2[0];
    const float T = tanh_threshold();
    const int n = n_steps ? n_steps[0] : 64;

    const int i = blockIdx.x * blockDim.x + tid;   // 1 agent per thread

    const float4 s = x[i];
    float p = s.x, v = s.y, u = s.z, a = s.w;

    if (b1_zero) run_agent<true >(wxy, wzh, wbb, bias2, T, n, p, v, u, a);
    else         run_agent<false>(wxy, wzh, wbb, bias2, T, n, p, v, u, a);

    out[i] = make_float4(p, v, u, a);
}

extern "C" void kernel_launch(void* const* d_in, const int* in_sizes, int n_in,
                              void* d_out, int out_size) {
    const float* x  = (const float*)d_in[0];
    const float* W1 = (const float*)d_in[1];
    const float* b1 = (const float*)d_in[2];
    const float* W2 = (const float*)d_in[3];
    const float* b2 = (const float*)d_in[4];
    const int* ns   = (n_in >= 6) ? (const int*)d_in[5] : nullptr;

    mc_kernel<<<NB / 64, 64>>>((const float4*)x, W1, b1, W2, b2, ns,
                               (float4*)d_out);
}

// round 15
// speedup vs baseline: 1.1256x; 1.1256x over previous
#include <cuda_runtime.h>
#include <cuda_bf16.h>
#include <math.h>

#define NB 65536
#define HALF 32768
#define LH 64
#define GOALC 0.5f
#define MINPC (-1.2f)
#define UTHRESH 0.5f

typedef unsigned long long u64;

// ---- packed f32x2 primitives (single-slot packed ops on sm_103a) ----
// PTX f32x2 supports ONLY add/mul/fma (R14 lesson: no max.f32x2).
__device__ __forceinline__ u64 pk2(float lo, float hi) {
    u64 r; asm("mov.b64 %0, {%1, %2};" : "=l"(r) : "f"(lo), "f"(hi)); return r;
}
__device__ __forceinline__ void upk2(u64 v, float& lo, float& hi) {
    asm("mov.b64 {%0, %1}, %2;" : "=f"(lo), "=f"(hi) : "l"(v));
}
__device__ __forceinline__ u64 mul2(u64 a, u64 b) {
    u64 r; asm("mul.rn.f32x2 %0, %1, %2;" : "=l"(r) : "l"(a), "l"(b)); return r;
}
__device__ __forceinline__ u64 fma2(u64 a, u64 b, u64 c) {
    u64 r; asm("fma.rn.f32x2 %0, %1, %2, %3;" : "=l"(r) : "l"(a), "l"(b), "l"(c)); return r;
}
__device__ __forceinline__ u64 add2(u64 a, u64 b) {
    u64 r; asm("add.rn.f32x2 %0, %1, %2;" : "=l"(r) : "l"(a), "l"(b)); return r;
}

#define ABSM2 0x7FFFFFFF7FFFFFFFULL  // per-lane |x|
#define SGN2  0x8000000080000000ULL  // per-lane sign flip = exact negation

// XLA / Eigen rational tanh approximation for f32 (matches reference lowering).
__device__ __forceinline__ float xla_tanh(float xin) {
    const float x = fminf(fmaxf(xin, -7.99881172180175781f), 7.99881172180175781f);
    const float x2 = __fmul_rn(x, x);
    float p = __fmaf_rn(x2, -2.76076847742355e-16f, 2.00018790482477e-13f);
    p = __fmaf_rn(x2, p, -8.60467152213735e-11f);
    p = __fmaf_rn(x2, p, 5.12229709037114e-08f);
    p = __fmaf_rn(x2, p, 1.48572235717979e-05f);
    p = __fmaf_rn(x2, p, 6.37261928875436e-04f);
    p = __fmaf_rn(x2, p, 4.89352455891786e-03f);
    p = __fmul_rn(x, p);
    float q = __fmaf_rn(x2, 1.19825839466702e-06f, 1.18534705686654e-04f);
    q = __fmaf_rn(x2, q, 2.26843463243900e-03f);
    q = __fmaf_rn(x2, q, 4.89352518554385e-03f);
    const float r = __fdiv_rn(p, q);
    return (fabsf(xin) < 0.0004f) ? xin : r;
}

// Largest float T in [0.4, 1.0] with xla_tanh(T) <= UTHRESH (bit bisection).
__device__ __forceinline__ float tanh_threshold() {
    unsigned a = __float_as_uint(0.4f);
    unsigned b = __float_as_uint(1.0f);
    while (b - a > 1u) {
        const unsigned m = a + (b - a) / 2u;
        if (xla_tanh(__uint_as_float(m)) <= UTHRESH) a = m; else b = m;
    }
    return __uint_as_float(a);
}

// Shared weight layout — packs unit j with j+4 (groups of 8):
//   pack m (m=0..31): g=m/4, a=m%4, j_lo=8g+a, j_hi=8g+a+4
//   wxy[m] = { {W1[0][j_lo],W1[0][j_hi]}, {W1[1][j_lo],W1[1][j_hi]} }
//   wz2[h] = { halfW2-pack for m=2h, halfW2-pack for m=2h+1 }  (W2/2, exact)
//   wb2[h] = { b1-pack for m=2h, b1-pack for m=2h+1 }
// Pack m accumulates into T[m%4] in increasing m -> scalar lane (j mod 8)
// receives its terms in increasing j, and the packed merge
//   add2(add2(T0,T1), add2(T2,T3)) -> {(l0+l1)+(l2+l3), (l4+l5)+(l6+l7)}
// reproduces R6's rn tree bit-exactly after unpack + one __fadd_rn.
template<bool B1_ZERO>
__device__ __forceinline__ void run_pair(
    const ulonglong2* __restrict__ wxy,
    const ulonglong2* __restrict__ wz2,
    const ulonglong2* __restrict__ wb2,
    float bias2, float T, int n,
    float& pA, float& vA, float& uA, float& aA,
    float& pB, float& vB, float& uB, float& aB)
{
    // packed constants (hoisted by ptxas)
    const u64 C3_2   = pk2(3.0f, 3.0f);
    const u64 TOPI2  = pk2(0.63661977236758134f, 0.63661977236758134f);
    const u64 MAGIC2 = pk2(12582912.0f, 12582912.0f);
    const u64 DP1_2  = pk2(1.5703125f, 1.5703125f);
    const u64 DP2_2  = pk2(4.837512969970703125e-4f, 4.837512969970703125e-4f);
    const u64 DP3_2  = pk2(7.549789948768648e-8f, 7.549789948768648e-8f);
    const u64 PC0_2  = pk2(-1.388731625493765e-3f, -1.388731625493765e-3f);
    const u64 PC1_2  = pk2(2.443315711809948e-5f, 2.443315711809948e-5f);
    const u64 PC2_2  = pk2(4.166664568298827e-2f, 4.166664568298827e-2f);
    const u64 NHALF2 = pk2(-0.5f, -0.5f);
    const u64 ONE2   = pk2(1.0f, 1.0f);
    const u64 PS0_2  = pk2(8.3321608736e-3f, 8.3321608736e-3f);
    const u64 PS1_2  = pk2(-1.9515295891e-4f, -1.9515295891e-4f);
    const u64 PS2_2  = pk2(-1.6666654611e-1f, -1.6666654611e-1f);
    const u64 C15_2  = pk2(0.0015f, 0.0015f);
    const u64 C25_2  = pk2(0.0025f, 0.0025f);

    float lastPreA = 0.0f, lastPreB = 0.0f;
    bool tookA = false, tookB = false;

    for (int t = 0; t < n; ++t) {
        const bool actA = (pA <= GOALC);
        const bool actB = (pB <= GOALC);
        if (!(actA || actB)) break;   // inactive is absorbing

        const bool rsA = (pA <= MINPC);
        const float prA = rsA ? MINPC : pA;
        const float vrA = rsA ? 0.0f : vA;
        const bool rsB = (pB <= MINPC);
        const float prB = rsB ? MINPC : pB;
        const float vrB = rsB ? 0.0f : vB;

        const u64 p2A = pk2(prA, prA), v2A = pk2(vrA, vrA);
        const u64 p2B = pk2(prB, prB), v2B = pk2(vrB, vrB);

        // 4 packed accumulators per agent; pack m -> T[m%4]
        u64 TA0 = 0, TA1 = 0, TA2 = 0, TA3 = 0;
        u64 TB0 = 0, TB1 = 0, TB2 = 0, TB3 = 0;
        #pragma unroll
        for (int h = 0; h < 16; ++h) {          // packs 2h, 2h+1 (4 units)
            const ulonglong2 xyE = wxy[2 * h];
            const ulonglong2 xyO = wxy[2 * h + 1];
            const ulonglong2 zz  = wz2[h];

            u64 dAE = fma2(v2A, xyE.y, mul2(p2A, xyE.x));
            u64 dAO = fma2(v2A, xyO.y, mul2(p2A, xyO.x));
            u64 dBE = fma2(v2B, xyE.y, mul2(p2B, xyE.x));
            u64 dBO = fma2(v2B, xyO.y, mul2(p2B, xyO.x));
            if (!B1_ZERO) {
                const ulonglong2 bb = wb2[h];
                dAE = add2(dAE, bb.x); dAO = add2(dAO, bb.y);
                dBE = add2(dBE, bb.x); dBO = add2(dBO, bb.y);
            }
            // relu via validated trick: fma(d+|d|, wz/2, T) == fma(relu(d), wz, T)
            const u64 rAE = add2(dAE, dAE & ABSM2);
            const u64 rAO = add2(dAO, dAO & ABSM2);
            const u64 rBE = add2(dBE, dBE & ABSM2);
            const u64 rBO = add2(dBO, dBO & ABSM2);

            if ((h & 1) == 0) {   // m=2h -> T0, m=2h+1 -> T1
                TA0 = fma2(rAE, zz.x, TA0); TA1 = fma2(rAO, zz.y, TA1);
                TB0 = fma2(rBE, zz.x, TB0); TB1 = fma2(rBO, zz.y, TB1);
            } else {              // m=2h -> T2, m=2h+1 -> T3
                TA2 = fma2(rAE, zz.x, TA2); TA3 = fma2(rAO, zz.y, TA3);
                TB2 = fma2(rBE, zz.x, TB2); TB3 = fma2(rBO, zz.y, TB3);
            }
        }

        // packed merge == R6 scalar rn tree (see layout comment)
        const u64 WA = add2(add2(TA0, TA1), add2(TA2, TA3));
        const u64 WB = add2(add2(TB0, TB1), add2(TB2, TB3));
        float wAl, wAh, wBl, wBh;
        upk2(WA, wAl, wAh);
        upk2(WB, wBl, wBh);
        const float preA = __fadd_rn(__fadd_rn(wAl, wAh), bias2);
        const float preB = __fadd_rn(__fadd_rn(wBl, wBh), bias2);

        // un via hoisted tanh threshold (validated bit-exact R9-R13)
        const float unA = (preA <= T) ? -1.0f : 1.0f;
        const float unB = (preB <= T) ? -1.0f : 1.0f;

        // ---- packed Cody-Waite cos for both agents (per-lane == scalar) ----
        const u64 pr2 = pk2(prA, prB);
        const u64 vr2 = pk2(vrA, vrB);
        const u64 arg2 = mul2(C3_2, pr2);
        const u64 m2  = mul2(arg2, TOPI2);
        // magic-number rint: bit-identical to rintf under rn/ties-even, |m| < 2^22
        const u64 kf2 = fma2(ONE2, add2(m2, MAGIC2), MAGIC2 ^ SGN2);
        const u64 nkf2 = kf2 ^ SGN2;                      // exact negation
        const u64 t2  = fma2(nkf2, DP1_2, arg2);
        const u64 rh2 = fma2(nkf2, DP2_2, t2);
        u64 rl2 = add2(add2(t2, rh2 ^ SGN2), mul2(kf2, DP2_2) ^ SGN2);
        rl2 = fma2(nkf2, DP3_2, rl2);
        const u64 z2 = mul2(rh2, rh2);

        u64 pc2 = fma2(z2, PC1_2, PC0_2);
        pc2 = fma2(z2, pc2, PC2_2);
        u64 c2 = fma2(z2, NHALF2, ONE2);
        c2 = fma2(mul2(z2, z2), pc2, c2);
        c2 = fma2(rl2 ^ SGN2, rh2, c2);

        u64 ps2 = fma2(z2, PS1_2, PS0_2);
        ps2 = fma2(z2, ps2, PS2_2);
        u64 s2 = fma2(mul2(rh2, z2), ps2, rl2);
        s2 = add2(rh2, s2);

        float kfA, kfB, cAc, cBc, sAs, sBs;
        upk2(kf2, kfA, kfB);
        upk2(c2, cAc, cBc);
        upk2(s2, sAs, sBs);
        const int qA = ((int)kfA) & 3;
        const int qB = ((int)kfB) & 3;
        float cA = (qA & 1) ? sAs : cAc;
        if (qA == 1 || qA == 2) cA = -cA;
        float cB = (qB & 1) ? sBs : cBc;
        if (qB == 1 || qB == 2) cB = -cB;

        // packed state update (per-lane identical to scalar sequence)
        const u64 un2 = pk2(unA, unB);
        const u64 cc2 = pk2(cA, cB);
        const u64 vn2 = add2(add2(vr2, mul2(un2, C15_2)),
                             mul2(C25_2, cc2) ^ SGN2);    // a-b == a+(-b), exact
        const u64 pn2 = add2(pr2, vn2);
        float vnA, vnB, pnA, pnB;
        upk2(vn2, vnA, vnB);
        upk2(pn2, pnA, pnB);

        if (actA) { pA = pnA; vA = vnA; uA = unA; lastPreA = preA; tookA = true; }
        if (actB) { pB = pnB; vB = vnB; uB = unB; lastPreB = preB; tookB = true; }
    }

    if (tookA) aA = xla_tanh(lastPreA);
    if (tookB) aB = xla_tanh(lastPreB);
}

__global__ __launch_bounds__(64)   // uncapped regs: weights hoist into registers
void mc_kernel(const float4* __restrict__ x,
               const float* __restrict__ W1,
               const float* __restrict__ b1,
               const float* __restrict__ W2,
               const float* __restrict__ b2,
               const int* __restrict__ n_steps,
               float4* __restrict__ out)
{
    __shared__ ulonglong2 wxy[32];
    __shared__ ulonglong2 wz2[16];
    __shared__ ulonglong2 wb2[16];

    const int tid = threadIdx.x;   // 0..63
    int zok = 1;
    if (tid < 32) {                // pack m = tid: g=m/4, a=m%4
        const int g = tid >> 2, a = tid & 3;
        const int jl = 8 * g + a, jh = jl + 4;
        wxy[tid] = make_ulonglong2(pk2(W1[jl], W1[jh]),
                                   pk2(W1[LH + jl], W1[LH + jh]));
        const float bl = b1[jl], bh = b1[jh];
        zok = (__float_as_uint(bl) == 0u) && (__float_as_uint(bh) == 0u);
        if ((tid & 1) == 0) {      // wz2[h]: halved W2 packs (exact scaling)
            const int h = tid >> 1;
            const int g0 = (2 * h) >> 2, a0 = (2 * h) & 3;
            const int g1 = (2 * h + 1) >> 2, a1 = (2 * h + 1) & 3;
            const int j0l = 8 * g0 + a0, j1l = 8 * g1 + a1;
            wz2[h] = make_ulonglong2(
                pk2(__fmul_rn(0.5f, W2[j0l]), __fmul_rn(0.5f, W2[j0l + 4])),
                pk2(__fmul_rn(0.5f, W2[j1l]), __fmul_rn(0.5f, W2[j1l + 4])));
            wb2[h] = make_ulonglong2(pk2(b1[j0l], b1[j0l + 4]),
                                     pk2(b1[j1l], b1[j1l + 4]));
        }
    }
    const int b1_zero = __syncthreads_and(zok);

    const float bias2 = b2[0];
    const float T = tanh_threshold();
    const int n = n_steps ? n_steps[0] : 64;

    const int iA = blockIdx.x * blockDim.x + tid;   // agents [0, 32768)
    const int iB = iA + HALF;                       // agents [32768, 65536)

    const float4 sA = x[iA];
    const float4 sB = x[iB];
    float pA = sA.x, vA = sA.y, uA = sA.z, aA = sA.w;
    float pB = sB.x, vB = sB.y, uB = sB.z, aB = sB.w;

    if (b1_zero) run_pair<true >(wxy, wz2, wb2, bias2, T, n, pA, vA, uA, aA, pB, vB, uB, aB);
    else         run_pair<false>(wxy, wz2, wb2, bias2, T, n, pA, vA, uA, aA, pB, vB, uB, aB);

    out[iA] = make_float4(pA, vA, uA, aA);
    out[iB] = make_float4(pB, vB, uB, aB);
}

extern "C" void kernel_launch(void* const* d_in, const int* in_sizes, int n_in,
                              void* d_out, int out_size) {
    const float* x  = (const float*)d_in[0];
    const float* W1 = (const float*)d_in[1];
    const float* b1 = (const float*)d_in[2];
    const float* W2 = (const float*)d_in[3];
    const float* b2 = (const float*)d_in[4];
    const int* ns   = (n_in >= 6) ? (const int*)d_in[5] : nullptr;

    mc_kernel<<<HALF / 64, 64>>>((const float4*)x, W1, b1, W2, b2, ns,
                                 (float4*)d_out);
}